// round 17
// baseline (speedup 1.0000x reference)
#include <cuda_runtime.h>
#include <math.h>

#define BB 8
#define C4v 64
#define OQ 16
#define NNv 512
#define LL 12
#define CCv (OQ * C4v)   // 1024

__device__ __forceinline__ unsigned f2tf(float f) {
    unsigned u; asm("cvt.rna.tf32.f32 %0, %1;" : "=r"(u) : "f"(f)); return u;
}
__device__ __forceinline__ float rnd_tf(float f) {
    return __uint_as_float(f2tf(f));
}
__device__ __forceinline__ void mma_tf32(float* c, const unsigned* a, const unsigned* b) {
    asm volatile(
        "mma.sync.aligned.m16n8k8.row.col.f32.tf32.tf32.f32 "
        "{%0,%1,%2,%3}, {%4,%5,%6,%7}, {%8,%9}, {%0,%1,%2,%3};"
        : "+f"(c[0]), "+f"(c[1]), "+f"(c[2]), "+f"(c[3])
        : "r"(a[0]), "r"(a[1]), "r"(a[2]), "r"(a[3]), "r"(b[0]), "r"(b[1]));
}
__device__ __forceinline__ void cpa16(void* dst_smem, const void* src) {
    unsigned d = (unsigned)__cvta_generic_to_shared(dst_smem);
    asm volatile("cp.async.cg.shared.global [%0], [%1], 16;" :: "r"(d), "l"(src));
}
// relu(tanh(x)) = tanh(max(x,0)); fast one-sided tanh for x>=0
__device__ __forceinline__ float tanh_relu(float x) {
    float m = fmaxf(x, 0.f);
    float e = __expf(-2.f * m);
    return __fdividef(1.f - e, 1.f + e);
}

// Scratch (device globals: allocation-free per harness rules)
__device__ float g_G[BB * NNv * CCv];   // [b][n][c'][c], tf32-rounded values
__device__ float g_Fl[BB * NNv * OQ];   // [b][n][c']
__device__ float g_ys[BB * OQ * NNv];   // [b][o][n]  per-n Fc row sumsq
__device__ float g_T[BB * NNv * NNv];   // [b][k][n], tf32-rounded values
__device__ float g_H[BB * NNv * CCv];   // [b][k][cc]
__device__ float g_invl2[BB];

// k1: block = (8 n's, b), 256 threads. Contiguous 384B x reads per c-row,
// xs padded to 97 (odd -> conflict-free for both the Fc and G loops).
// No atomics: Fl and per-n ys stored for k1b to reduce.
__global__ void __launch_bounds__(256) k1(const float* __restrict__ x,
                                          const float* __restrict__ Wc,
                                          const float* __restrict__ bc) {
    int n0 = blockIdx.x * 8, b = blockIdx.y;
    __shared__ float xs[C4v * 97];   // [c][n*12+l], 24.8 KB
    __shared__ float Ws[OQ * C4v];   // 4 KB
    __shared__ float Fc[OQ * 96];    // [o][n*12+l], 6 KB
    int t = threadIdx.x;

    // load x: 64 c-rows of 96 contiguous floats (24 float4 each)
    for (int i = t; i < C4v * 24; i += 256) {
        int c = i / 24, j = i % 24;
        float4 v = __ldg((const float4*)(x + ((size_t)(b * C4v + c) * NNv + n0) * LL) + j);
        float* dst = xs + c * 97 + j * 4;
        dst[0] = v.x; dst[1] = v.y; dst[2] = v.z; dst[3] = v.w;
    }
    for (int i = t; i < OQ * C4v; i += 256) Ws[i] = Wc[i];
    __syncthreads();

    // Fc[o][nl] = bc[o] + sum_c Ws[o][c]*xs[c][nl]
    for (int i = t; i < OQ * 96; i += 256) {
        int o = i / 96, nl = i % 96;
        float s = bc[o];
        #pragma unroll 16
        for (int c = 0; c < C4v; c++) s += Ws[o * C4v + c] * xs[c * 97 + nl];
        Fc[i] = s;
    }
    __syncthreads();

    // G[b][n0+n][o][c] = sum_l Fc[o][n*12+l]*xs[c][n*12+l] (tf32-rounded)
    for (int i = t; i < 8 * CCv; i += 256) {
        int n = i >> 10, oc = i & 1023;
        int o = oc >> 6, c = oc & 63;
        float s = 0.f;
        #pragma unroll
        for (int l = 0; l < LL; l++)
            s += Fc[o * 96 + n * LL + l] * xs[c * 97 + n * LL + l];
        g_G[((size_t)(b * NNv + n0 + n)) * CCv + oc] = rnd_tf(s);
    }
    // Fl + ys (no atomics)
    if (t < 128) {
        int o = t >> 3, n = t & 7;
        float fl = Fc[o * 96 + n * LL + (LL - 1)];
        g_Fl[((size_t)(b * NNv + n0 + n)) * OQ + o] = fl;
        float ys = 0.f;
        #pragma unroll
        for (int l = 0; l < LL; l++) {
            float v = Fc[o * 96 + n * LL + l];
            ys += v * v;
        }
        g_ys[((size_t)b * OQ + o) * NNv + n0 + n] = ys;
    }
}

// k1b: xx[o] = sum_n Fl[n][o]^2 ; yy[o] = sum_n ys[o][n] ;
//      invl2[b] = 1 / sum_o sqrt(xx)*sqrt(yy)
__global__ void k1b() {
    int b = blockIdx.x;
    int t = threadIdx.x;  // 256
    __shared__ float sxx[OQ][17], syy[OQ][17];
    __shared__ float vo[OQ];
    int o = t >> 4, ch = t & 15;  // 16 chunks x 32 n
    float xx = 0.f, yy = 0.f;
    for (int j = 0; j < 32; j++) {
        int n = ch * 32 + j;
        float fl = g_Fl[((size_t)(b * NNv + n)) * OQ + o];
        xx += fl * fl;
        yy += g_ys[((size_t)b * OQ + o) * NNv + n];
    }
    sxx[o][ch] = xx; syy[o][ch] = yy;
    __syncthreads();
    if (t < OQ) {
        float axx = 0.f, ayy = 0.f;
        #pragma unroll
        for (int j = 0; j < 16; j++) { axx += sxx[t][j]; ayy += syy[t][j]; }
        vo[t] = sqrtf(axx) * sqrtf(ayy);
    }
    __syncthreads();
    if (t == 0) {
        float s = 0.f;
        #pragma unroll
        for (int j = 0; j < OQ; j++) s += vo[j];
        g_invl2[b] = 1.0f / s;
    }
}

// k2 on TENSOR CORES: per (b,p): R[q][c] = sum_o Fl[q][o]*G[p][o][c],
// then T[p][q] = relu(tanh(inv * max_c R)). 2 p per warp (16 p per block);
// A-frags from Fls (pad 20, conflict-free) amortized over both p's.
__global__ void __launch_bounds__(256, 2) k2tc() {
    int p0 = blockIdx.x * 16, b = blockIdx.y;
    __shared__ unsigned Fls[NNv * 20];   // [q][o] tf32, 40 KB
    int t = threadIdx.x;
    int lane = t & 31, w = t >> 5;
    int g = lane >> 2, tg = lane & 3;
    int pA = p0 + 2 * w, pB = pA + 1;

    {
        const float4* src = (const float4*)(g_Fl + (size_t)b * NNv * OQ);
        for (int i = t; i < NNv * OQ / 4; i += 256) {
            float4 v = __ldg(src + i);
            int q = i >> 2, o4 = (i & 3) * 4;
            unsigned* dst = Fls + q * 20 + o4;
            dst[0] = f2tf(v.x); dst[1] = f2tf(v.y);
            dst[2] = f2tf(v.z); dst[3] = f2tf(v.w);
        }
    }

    const float* GA = g_G + ((size_t)b * NNv + pA) * CCv;
    const float* GB = g_G + ((size_t)b * NNv + pB) * CCv;
    unsigned bfA[8][2][2], bfB[8][2][2];
    #pragma unroll
    for (int j = 0; j < 8; j++)
        #pragma unroll
        for (int ks = 0; ks < 2; ks++) {
            bfA[j][ks][0] = __float_as_uint(__ldg(GA + (ks * 8 + tg) * C4v + j * 8 + g));
            bfA[j][ks][1] = __float_as_uint(__ldg(GA + (ks * 8 + tg + 4) * C4v + j * 8 + g));
            bfB[j][ks][0] = __float_as_uint(__ldg(GB + (ks * 8 + tg) * C4v + j * 8 + g));
            bfB[j][ks][1] = __float_as_uint(__ldg(GB + (ks * 8 + tg + 4) * C4v + j * 8 + g));
        }
    __syncthreads();

    float inv = g_invl2[b];
    float* TrA = g_T + ((size_t)b * NNv + pA) * NNv;
    float* TrB = g_T + ((size_t)b * NNv + pB) * NNv;

    for (int mt = 0; mt < 32; mt++) {
        unsigned a[2][4];
        int r = mt * 16 + g;
        #pragma unroll
        for (int ks = 0; ks < 2; ks++) {
            a[ks][0] = Fls[r * 20 + ks * 8 + tg];
            a[ks][1] = Fls[(r + 8) * 20 + ks * 8 + tg];
            a[ks][2] = Fls[r * 20 + ks * 8 + tg + 4];
            a[ks][3] = Fls[(r + 8) * 20 + ks * 8 + tg + 4];
        }
        #pragma unroll
        for (int pp = 0; pp < 2; pp++) {
            float acc[8][4];
            #pragma unroll
            for (int j = 0; j < 8; j++)
                #pragma unroll
                for (int e = 0; e < 4; e++) acc[j][e] = 0.f;
            #pragma unroll
            for (int j = 0; j < 8; j++) {
                if (pp == 0) {
                    mma_tf32(acc[j], a[0], bfA[j][0]);
                    mma_tf32(acc[j], a[1], bfA[j][1]);
                } else {
                    mma_tf32(acc[j], a[0], bfB[j][0]);
                    mma_tf32(acc[j], a[1], bfB[j][1]);
                }
            }
            float m0 = -1e30f, m1 = -1e30f;
            #pragma unroll
            for (int j = 0; j < 8; j++) {
                m0 = fmaxf(m0, fmaxf(acc[j][0], acc[j][1]));
                m1 = fmaxf(m1, fmaxf(acc[j][2], acc[j][3]));
            }
            m0 = fmaxf(m0, __shfl_xor_sync(0xffffffffu, m0, 1));
            m0 = fmaxf(m0, __shfl_xor_sync(0xffffffffu, m0, 2));
            m1 = fmaxf(m1, __shfl_xor_sync(0xffffffffu, m1, 1));
            m1 = fmaxf(m1, __shfl_xor_sync(0xffffffffu, m1, 2));
            if (tg == 0) {
                float* Tr = pp ? TrB : TrA;
                Tr[mt * 16 + g]     = rnd_tf(tanh_relu(m0 * inv));
                Tr[mt * 16 + 8 + g] = rnd_tf(tanh_relu(m1 * inv));
            }
        }
    }
}

// k3: per-b tf32 GEMM  H[k][cc] = sum_n T[k][n] * G[n][cc].
// Operands pre-rounded to tf32 -> staging is pure cp.async, double-buffered.
__global__ void __launch_bounds__(256, 2) k3() {
    int b = blockIdx.z;
    int cc0 = blockIdx.y * 128;
    int k0 = blockIdx.x * 128;
    const float* Am = g_T + (size_t)b * NNv * NNv;  // [k][n]
    const float* Bm = g_G + (size_t)b * NNv * CCv;  // [n][cc]
    float* Cm = g_H + (size_t)b * NNv * CCv;        // [k][cc]

    __shared__ float As[2][128][36];
    __shared__ float Bs[2][32][136];

    int t = threadIdx.x;
    int lane = t & 31, w = t >> 5;
    int g = lane >> 2, tg = lane & 3;
    int wm = (w & 3) * 32;
    int wn = (w >> 2) * 64;

    float c[2][8][4];
    #pragma unroll
    for (int i = 0; i < 2; i++)
        #pragma unroll
        for (int j = 0; j < 8; j++)
            #pragma unroll
            for (int e = 0; e < 4; e++) c[i][j][e] = 0.f;

    int s_arow = t >> 3, s_ac4 = (t & 7) * 4;
    int s_brow = t >> 5, s_bc4 = (t & 31) * 4;

    #pragma unroll
    for (int pass = 0; pass < 4; pass++) {
        int ar = s_arow + pass * 32;
        cpa16(&As[0][ar][s_ac4], Am + (size_t)(k0 + ar) * NNv + s_ac4);
        int br = s_brow + pass * 8;
        cpa16(&Bs[0][br][s_bc4], Bm + (size_t)br * CCv + cc0 + s_bc4);
    }
    asm volatile("cp.async.commit_group;");

    int buf = 0;
    for (int n0 = 0; n0 < NNv; n0 += 32) {
        bool has_next = (n0 + 32) < NNv;
        if (has_next) {
            int nb = buf ^ 1, nn0 = n0 + 32;
            #pragma unroll
            for (int pass = 0; pass < 4; pass++) {
                int ar = s_arow + pass * 32;
                cpa16(&As[nb][ar][s_ac4], Am + (size_t)(k0 + ar) * NNv + nn0 + s_ac4);
                int br = s_brow + pass * 8;
                cpa16(&Bs[nb][br][s_bc4], Bm + (size_t)(nn0 + br) * CCv + cc0 + s_bc4);
            }
            asm volatile("cp.async.commit_group;");
            asm volatile("cp.async.wait_group 1;");
        } else {
            asm volatile("cp.async.wait_group 0;");
        }
        __syncthreads();
        #pragma unroll
        for (int k8 = 0; k8 < 4; k8++) {
            unsigned a[2][4], bb[8][2];
            #pragma unroll
            for (int i = 0; i < 2; i++) {
                int r = wm + i * 16 + g;
                a[i][0] = __float_as_uint(As[buf][r][k8 * 8 + tg]);
                a[i][1] = __float_as_uint(As[buf][r + 8][k8 * 8 + tg]);
                a[i][2] = __float_as_uint(As[buf][r][k8 * 8 + tg + 4]);
                a[i][3] = __float_as_uint(As[buf][r + 8][k8 * 8 + tg + 4]);
            }
            #pragma unroll
            for (int j = 0; j < 8; j++) {
                bb[j][0] = __float_as_uint(Bs[buf][k8 * 8 + tg][wn + j * 8 + g]);
                bb[j][1] = __float_as_uint(Bs[buf][k8 * 8 + tg + 4][wn + j * 8 + g]);
            }
            #pragma unroll
            for (int i = 0; i < 2; i++)
                #pragma unroll
                for (int j = 0; j < 8; j++)
                    mma_tf32(c[i][j], a[i], bb[j]);
        }
        __syncthreads();
        buf ^= 1;
    }
    #pragma unroll
    for (int i = 0; i < 2; i++) {
        int r0 = k0 + wm + i * 16 + g;
        #pragma unroll
        for (int j = 0; j < 8; j++) {
            int col = cc0 + wn + j * 8 + tg * 2;
            *(float2*)(Cm + (size_t)r0 * CCv + col) =
                make_float2(c[i][j][0], c[i][j][1]);
            *(float2*)(Cm + (size_t)(r0 + 8) * CCv + col) =
                make_float2(c[i][j][2], c[i][j][3]);
        }
    }
}

// k4: block = (16-k chunk, b), 256 threads. Stage Wg once per block;
// phase1 xg, phase2 64x64x16 output GEMM.
__global__ void __launch_bounds__(256) k4(const float* __restrict__ Wg,
                                          const float* __restrict__ bg,
                                          float* __restrict__ out) {
    int k0 = blockIdx.x * 16, b = blockIdx.y;
    __shared__ float Wgs[C4v * 65];
    __shared__ float xg[16][65];
    __shared__ float Flk[16][OQ];
    int t = threadIdx.x;  // 256

    for (int i = t; i < C4v * C4v; i += 256)
        Wgs[(i >> 6) * 65 + (i & 63)] = Wg[i];
    if (t < 64)
        ((float4*)&Flk[0][0])[t] =
            ((const float4*)(g_Fl + ((size_t)b * NNv + k0) * OQ))[t];
    __syncthreads();

    float inv = g_invl2[b];
    {
        int k = t >> 4;
        int cg = (t & 15) * 4;
        const float4* Hrow =
            (const float4*)(g_H + ((size_t)b * NNv + k0 + k) * CCv);
        float s[4] = {0.f, 0.f, 0.f, 0.f};
        #pragma unroll 4
        for (int o = 0; o < OQ; o++) {
            float fl = Flk[k][o];
            float4 h = __ldg(Hrow + o * 16 + (cg >> 2));
            s[0] += fl * h.x; s[1] += fl * h.y;
            s[2] += fl * h.z; s[3] += fl * h.w;
        }
        #pragma unroll
        for (int j = 0; j < 4; j++) xg[k][cg + j] = s[j] * inv;
    }
    __syncthreads();
    {
        int o2 = t >> 2;
        int kg = (t & 3) * 4;
        float s[4];
        float bias = bg[o2];
        #pragma unroll
        for (int j = 0; j < 4; j++) s[j] = bias;
        #pragma unroll 8
        for (int c = 0; c < C4v; c++) {
            float w = Wgs[o2 * 65 + c];
            #pragma unroll
            for (int j = 0; j < 4; j++) s[j] += w * xg[kg + j][c];
        }
        float* dst = out + ((size_t)b * C4v + o2) * NNv + k0 + kg;
        #pragma unroll
        for (int j = 0; j < 4; j++) dst[j] = s[j];
    }
}

extern "C" void kernel_launch(void* const* d_in, const int* in_sizes, int n_in,
                              void* d_out, int out_size) {
    const float* x  = (const float*)d_in[0];
    const float* Wc = (const float*)d_in[1];
    const float* bc = (const float*)d_in[2];
    const float* Wg = (const float*)d_in[3];
    const float* bg = (const float*)d_in[4];
    float* out = (float*)d_out;

    k1<<<dim3(NNv / 8, BB), 256>>>(x, Wc, bc);
    k1b<<<BB, 256>>>();
    k2tc<<<dim3(NNv / 16, BB), 256>>>();
    k3<<<dim3(NNv / 128, CCv / 128, BB), 256>>>();
    k4<<<dim3(NNv / 16, BB), 256>>>(Wg, bg, out);
}